// round 3
// baseline (speedup 1.0000x reference)
#include <cuda_runtime.h>
#include <math.h>
#include <stdint.h>

#define Bn 1024
#define Tn 64
#define Dn 512
#define Hn 512
#define Cn 96
#define Sn 21
#define DCn (Dn + Cn)   // 608
#define XCn (Dn + Hn)   // 1024

// ---------------- scratch (device globals) ----------------
__device__ float g_Hp[(size_t)Bn * Tn * Hn];       // 128 MB
__device__ float g_c[Bn * Hn];
__device__ float g_ph[2 * Bn * Hn];                // two split-K halves
__device__ float g_xcat[Bn * XCn];                 // [ctx | h]
__device__ float g_hs[(size_t)Bn * Sn * Hn];
__device__ float g_Wcat[(size_t)4 * Hn * XCn];     // interleaved rows j=4n+gate
__device__ float g_ohb[Cn * 4 * Hn];               // interleaved, + biases

// ---------------- helpers ----------------
__device__ __forceinline__ float tanh_fast(float x) {
    float y;
    asm("tanh.approx.f32 %0, %1;" : "=f"(y) : "f"(x));
    return y;
}
__device__ __forceinline__ float sigmoidf(float x) {
    return 1.0f / (1.0f + expf(-x));
}
__device__ __forceinline__ uint32_t f2tf(float x) {
    uint32_t u;
    asm("cvt.rna.tf32.f32 %0, %1;" : "=r"(u) : "f"(x));
    return u;
}

// ---------------- init ----------------
__global__ void init_state_kernel() {
    int i = blockIdx.x * blockDim.x + threadIdx.x;
    if (i < Bn * Hn) { g_c[i] = 0.0f; g_xcat[(i / Hn) * XCn + Dn + (i % Hn)] = 0.0f; }
}

// ---------------- prep: Wcat (gate-interleaved) + ohb ----------------
__global__ void build_wcat_kernel(const float* __restrict__ Wih,
                                  const float* __restrict__ Whh) {
    int idx = blockIdx.x * blockDim.x + threadIdx.x;
    if (idx >= 4 * Hn * XCn) return;
    int j = idx >> 10;            // interleaved row [0,2048)
    int k = idx & 1023;
    int gate = j & 3, n = j >> 2;
    int r = gate * Hn + n;        // original row
    float v = (k < Dn) ? Wih[(size_t)r * DCn + k] : Whh[(size_t)r * Hn + (k - Dn)];
    g_Wcat[idx] = v;
}
__global__ void build_ohb_kernel(const float* __restrict__ Wih,
                                 const float* __restrict__ bih,
                                 const float* __restrict__ bhh) {
    int idx = blockIdx.x * blockDim.x + threadIdx.x;
    if (idx >= Cn * 4 * Hn) return;
    int c = idx / (4 * Hn);
    int j = idx % (4 * Hn);
    int gate = j & 3, n = j >> 2;
    int r = gate * Hn + n;
    g_ohb[idx] = Wih[(size_t)r * DCn + Dn + c] + bih[r] + bhh[r];
}

// ---------------- tf32 tensor-core GEMM, 2-stage smem pipeline ----------------
// C[m,n] = sum_k A[m,k]*B[n,k]. Tile 128x64x32, 256 thr, warps 4m x 2n (32x32).
// MODE: 0 = plain store, 1 = +bias (bias only if non-null; z-split support),
//       2 = +bias with N guard (ragged N), 3 = fused LSTM epilogue (no C write).
// gridDim.z>1 (MODE 1): each z does K elems starting at z*K; C offset z*M*ldc; bias z=0 only.
#define SM_A (128 * 36)
#define SM_B (64 * 36)
#define SMEM_BYTES ((2 * SM_A + 2 * SM_B) * 4)   // 55296

template <int MODE>
__global__ __launch_bounds__(256)
void gemm_core(const float* __restrict__ A, int lda,
               const float* __restrict__ B, int ldb,
               const float* __restrict__ bias,
               float* __restrict__ C, int ldc,
               int M, int Np, int K,
               const int* __restrict__ text, int s)
{
    extern __shared__ uint32_t sm[];
    uint32_t* AsBuf[2] = { sm, sm + SM_A };
    uint32_t* BsBuf[2] = { sm + 2 * SM_A, sm + 2 * SM_A + SM_B };

    const int tid = threadIdx.x;
    const int warp = tid >> 5, lane = tid & 31;
    const int g = lane >> 2, tig = lane & 3;
    const int wm = warp >> 1, wn = warp & 1;
    const int m0 = blockIdx.y * 128, n0 = blockIdx.x * 64;

    if (MODE == 1) {
        int z = blockIdx.z;
        A += (size_t)z * K;
        B += (size_t)z * K;
        C += (size_t)z * M * ldc;
        if (z != 0) bias = nullptr;
    }

    const float* Aptr = A + (size_t)m0 * lda;
    const float* Bptr = B + (size_t)n0 * ldb;

    float4 pa[4], pb[2];
    float acc[2][4][4];
#pragma unroll
    for (int i = 0; i < 2; i++)
#pragma unroll
        for (int j = 0; j < 4; j++)
#pragma unroll
            for (int l = 0; l < 4; l++) acc[i][j][l] = 0.0f;

    const int ntiles = K >> 5;

    auto loadAB = [&](int k0) {
#pragma unroll
        for (int v = 0; v < 4; v++) {
            int f = tid + v * 256;
            pa[v] = *reinterpret_cast<const float4*>(Aptr + (size_t)(f >> 3) * lda + k0 + ((f & 7) << 2));
        }
#pragma unroll
        for (int v = 0; v < 2; v++) {
            int f = tid + v * 256;
            int r = f >> 3;
            if (MODE == 2 && n0 + r >= Np)
                pb[v] = make_float4(0.f, 0.f, 0.f, 0.f);
            else
                pb[v] = *reinterpret_cast<const float4*>(Bptr + (size_t)r * ldb + k0 + ((f & 7) << 2));
        }
    };
    auto storeAB = [&](int buf) {
        uint32_t* As = AsBuf[buf];
        uint32_t* Bs = BsBuf[buf];
#pragma unroll
        for (int v = 0; v < 4; v++) {
            int f = tid + v * 256; int r = f >> 3, c = (f & 7) << 2;
            uint4 q = make_uint4(f2tf(pa[v].x), f2tf(pa[v].y), f2tf(pa[v].z), f2tf(pa[v].w));
            *reinterpret_cast<uint4*>(&As[r * 36 + c]) = q;
        }
#pragma unroll
        for (int v = 0; v < 2; v++) {
            int f = tid + v * 256; int r = f >> 3, c = (f & 7) << 2;
            uint4 q = make_uint4(f2tf(pb[v].x), f2tf(pb[v].y), f2tf(pb[v].z), f2tf(pb[v].w));
            *reinterpret_cast<uint4*>(&Bs[r * 36 + c]) = q;
        }
    };

    loadAB(0);
    storeAB(0);
    __syncthreads();

    for (int t = 0; t < ntiles; t++) {
        const int cur = t & 1;
        if (t + 1 < ntiles) loadAB((t + 1) << 5);

        const uint32_t* As = AsBuf[cur];
        const uint32_t* Bs = BsBuf[cur];
#pragma unroll
        for (int ks = 0; ks < 4; ks++) {
            const int kk = ks * 8;
            uint32_t af[2][4], bf[4][2];
#pragma unroll
            for (int mt = 0; mt < 2; mt++) {
                int mb = wm * 32 + mt * 16;
                af[mt][0] = As[(mb + g) * 36 + kk + tig];
                af[mt][1] = As[(mb + g + 8) * 36 + kk + tig];
                af[mt][2] = As[(mb + g) * 36 + kk + tig + 4];
                af[mt][3] = As[(mb + g + 8) * 36 + kk + tig + 4];
            }
#pragma unroll
            for (int nt = 0; nt < 4; nt++) {
                int nb = wn * 32 + nt * 8 + g;
                bf[nt][0] = Bs[nb * 36 + kk + tig];
                bf[nt][1] = Bs[nb * 36 + kk + tig + 4];
            }
#pragma unroll
            for (int mt = 0; mt < 2; mt++)
#pragma unroll
                for (int nt = 0; nt < 4; nt++)
                    asm volatile(
                        "mma.sync.aligned.m16n8k8.row.col.f32.tf32.tf32.f32 "
                        "{%0,%1,%2,%3}, {%4,%5,%6,%7}, {%8,%9}, {%0,%1,%2,%3};"
                        : "+f"(acc[mt][nt][0]), "+f"(acc[mt][nt][1]),
                          "+f"(acc[mt][nt][2]), "+f"(acc[mt][nt][3])
                        : "r"(af[mt][0]), "r"(af[mt][1]), "r"(af[mt][2]), "r"(af[mt][3]),
                          "r"(bf[nt][0]), "r"(bf[nt][1]));
        }
        if (t + 1 < ntiles) storeAB(cur ^ 1);
        __syncthreads();
    }

    if (MODE == 3) {
        // ------- fused LSTM epilogue -------
        // stage gates tile [128 b][64 interleaved cols] into smem (reuse A buffers)
        float* gbuf = reinterpret_cast<float*>(sm);   // [128][72], 36864 B <= 2*SM_A*4
#pragma unroll
        for (int mt = 0; mt < 2; mt++) {
            int row = wm * 32 + mt * 16 + g;
#pragma unroll
            for (int nt = 0; nt < 4; nt++) {
                int col = wn * 32 + nt * 8 + 2 * tig;
                gbuf[row * 72 + col]       = acc[mt][nt][0];
                gbuf[row * 72 + col + 1]   = acc[mt][nt][1];
                gbuf[(row + 8) * 72 + col]     = acc[mt][nt][2];
                gbuf[(row + 8) * 72 + col + 1] = acc[mt][nt][3];
            }
        }
        __syncthreads();
#pragma unroll
        for (int p = 0; p < 8; p++) {
            int idx = p * 256 + tid;
            int bl = idx >> 4, nl = idx & 15;
            int b = m0 + bl;
            int ng = (n0 >> 2) + nl;
            float4 gv = *reinterpret_cast<const float4*>(&gbuf[bl * 72 + 4 * nl]);
            int tok = text[b * Sn + s];
            float4 ov = *reinterpret_cast<const float4*>(&g_ohb[(size_t)tok * 4 * Hn + 4 * ng]);
            float ig = gv.x + ov.x;
            float fg = gv.y + ov.y;
            float gg = gv.z + ov.z;
            float og = gv.w + ov.w;
            float c_old = g_c[b * Hn + ng];
            float cn = sigmoidf(fg) * c_old + sigmoidf(ig) * tanhf(gg);
            float hn = sigmoidf(og) * tanhf(cn);
            g_c[b * Hn + ng] = cn;
            g_xcat[b * XCn + Dn + ng] = hn;
            g_hs[((size_t)b * Sn + s) * Hn + ng] = hn;
        }
        return;
    }

    // ------- standard epilogue -------
#pragma unroll
    for (int mt = 0; mt < 2; mt++) {
        int row = m0 + wm * 32 + mt * 16 + g;
#pragma unroll
        for (int nt = 0; nt < 4; nt++) {
            int col = n0 + wn * 32 + nt * 8 + 2 * tig;
            if (MODE == 2 && col >= Np) continue;
            float b0 = 0.f, b1 = 0.f;
            if ((MODE == 1 || MODE == 2) && bias) { b0 = bias[col]; b1 = bias[col + 1]; }
            float2 v0 = make_float2(acc[mt][nt][0] + b0, acc[mt][nt][1] + b1);
            float2 v1 = make_float2(acc[mt][nt][2] + b0, acc[mt][nt][3] + b1);
            *reinterpret_cast<float2*>(&C[(size_t)row * ldc + col]) = v0;
            *reinterpret_cast<float2*>(&C[(size_t)(row + 8) * ldc + col]) = v1;
        }
    }
}

// ---------------- fused attention ----------------
__global__ __launch_bounds__(256)
void attn_kernel(const float* __restrict__ batch_H,
                 const float* __restrict__ Ws)
{
    const int b = blockIdx.x;
    __shared__ float ph_s[Hn];
    __shared__ float ws_s[Hn];
    __shared__ float e_s[Tn];
    __shared__ float alpha_s[Tn];

    const int tid = threadIdx.x;
    for (int i = tid; i < Hn; i += 256) {
        ph_s[i] = g_ph[b * Hn + i] + g_ph[Bn * Hn + b * Hn + i];
        ws_s[i] = Ws[i];
    }
    __syncthreads();

    const int warp = tid >> 5, lane = tid & 31;
    const float* hp_b = &g_Hp[(size_t)b * Tn * Hn];

    for (int t = warp; t < Tn; t += 8) {
        const float* hp = hp_b + t * Hn;
        float a = 0.0f;
#pragma unroll 4
        for (int h = lane; h < Hn; h += 32)
            a = fmaf(tanh_fast(hp[h] + ph_s[h]), ws_s[h], a);
#pragma unroll
        for (int o = 16; o > 0; o >>= 1)
            a += __shfl_xor_sync(0xffffffffu, a, o);
        if (lane == 0) e_s[t] = a;
    }
    __syncthreads();

    if (warp == 0) {
        float e0 = e_s[lane], e1 = e_s[lane + 32];
        float m = fmaxf(e0, e1);
#pragma unroll
        for (int o = 16; o > 0; o >>= 1)
            m = fmaxf(m, __shfl_xor_sync(0xffffffffu, m, o));
        float x0 = expf(e0 - m), x1 = expf(e1 - m);
        float sum = x0 + x1;
#pragma unroll
        for (int o = 16; o > 0; o >>= 1)
            sum += __shfl_xor_sync(0xffffffffu, sum, o);
        float inv = 1.0f / sum;
        alpha_s[lane] = x0 * inv;
        alpha_s[lane + 32] = x1 * inv;
    }
    __syncthreads();

    const float* bhp = &batch_H[(size_t)b * Tn * Dn];
    float a0 = 0.0f, a1 = 0.0f;
#pragma unroll 8
    for (int t = 0; t < Tn; t++) {
        float al = alpha_s[t];
        a0 = fmaf(al, bhp[t * Dn + tid], a0);
        a1 = fmaf(al, bhp[t * Dn + tid + 256], a1);
    }
    g_xcat[b * XCn + tid] = a0;
    g_xcat[b * XCn + tid + 256] = a1;
}

// ---------------- launch ----------------
extern "C" void kernel_launch(void* const* d_in, const int* in_sizes, int n_in,
                              void* d_out, int out_size)
{
    const float* batch_H = (const float*)d_in[0];
    const int*   text    = (const int*)  d_in[1];
    const float* Wi      = (const float*)d_in[2];
    const float* Wh      = (const float*)d_in[3];
    const float* bh      = (const float*)d_in[4];
    const float* Ws      = (const float*)d_in[5];
    const float* Wih     = (const float*)d_in[6];
    const float* Whh     = (const float*)d_in[7];
    const float* bih     = (const float*)d_in[8];
    const float* bhh     = (const float*)d_in[9];
    const float* Wg      = (const float*)d_in[10];
    const float* bg      = (const float*)d_in[11];
    float* out = (float*)d_out;

    float *Hp, *ph, *xcat, *hs, *Wcat;
    cudaGetSymbolAddress((void**)&Hp,   g_Hp);
    cudaGetSymbolAddress((void**)&ph,   g_ph);
    cudaGetSymbolAddress((void**)&xcat, g_xcat);
    cudaGetSymbolAddress((void**)&hs,   g_hs);
    cudaGetSymbolAddress((void**)&Wcat, g_Wcat);

    cudaFuncSetAttribute(gemm_core<0>, cudaFuncAttributeMaxDynamicSharedMemorySize, SMEM_BYTES);
    cudaFuncSetAttribute(gemm_core<1>, cudaFuncAttributeMaxDynamicSharedMemorySize, SMEM_BYTES);
    cudaFuncSetAttribute(gemm_core<2>, cudaFuncAttributeMaxDynamicSharedMemorySize, SMEM_BYTES);
    cudaFuncSetAttribute(gemm_core<3>, cudaFuncAttributeMaxDynamicSharedMemorySize, SMEM_BYTES);

    init_state_kernel<<<(Bn * Hn + 255) / 256, 256>>>();
    build_wcat_kernel<<<(4 * Hn * XCn + 255) / 256, 256>>>(Wih, Whh);
    build_ohb_kernel<<<(Cn * 4 * Hn + 255) / 256, 256>>>(Wih, bih, bhh);

    // Hp = batch_H @ Wi^T   [65536 x 512]
    gemm_core<0><<<dim3(Hn / 64, (Bn * Tn) / 128), 256, SMEM_BYTES>>>(
        batch_H, Dn, Wi, Dn, nullptr, Hp, Hn, Bn * Tn, Hn, Dn, nullptr, 0);

    for (int s = 0; s < Sn; s++) {
        // ph halves: z in {0,1}, K=256 each; bias on z=0
        gemm_core<1><<<dim3(Hn / 64, Bn / 128, 2), 256, SMEM_BYTES>>>(
            xcat + Dn, XCn, Wh, Hn, bh, ph, Hn, Bn, Hn, 256, nullptr, 0);

        attn_kernel<<<Bn, 256>>>(batch_H, Ws);

        // gates (interleaved) + fused LSTM
        gemm_core<3><<<dim3(4 * Hn / 64, Bn / 128), 256, SMEM_BYTES>>>(
            xcat, XCn, Wcat, XCn, nullptr, nullptr, 0, Bn, 4 * Hn, XCn, text, s);
    }

    // probs = hs @ Wg^T + bg   [21504 x 96], tf32 with ragged-N guard
    gemm_core<2><<<dim3(2, (Bn * Sn) / 128), 256, SMEM_BYTES>>>(
        hs, Hn, Wg, Hn, bg, out, Cn, Bn * Sn, Cn, Hn, nullptr, 0);
}

// round 5
// speedup vs baseline: 1.2982x; 1.2982x over previous
#include <cuda_runtime.h>
#include <cuda_fp16.h>
#include <math.h>
#include <stdint.h>

#define Bn 1024
#define Tn 64
#define Dn 512
#define Hn 512
#define Cn 96
#define Sn 21
#define DCn (Dn + Cn)   // 608
#define XCn (Dn + Hn)   // 1024

// ---------------- scratch (device globals) ----------------
__device__ __half g_Hp16[(size_t)Bn * Tn * Hn];     // 67 MB, attention score input
__device__ __half g_bh16[(size_t)Bn * Tn * Dn];     // 67 MB, ctx accumulation input
__device__ float  g_c[Bn * Hn];
__device__ float  g_ph[2 * Bn * Hn];                // split-K halves
__device__ float  g_xcat[Bn * XCn];                 // [ctx | h] fp32
__device__ float  g_hs[(size_t)Bn * Sn * Hn];       // fp32 (output path)
__device__ float  g_Wcat[(size_t)4 * Hn * XCn];     // interleaved rows j=4n+gate
__device__ float  g_ohb[Cn * 4 * Hn];               // Wih one-hot col + biases, interleaved

// ---------------- helpers ----------------
__device__ __forceinline__ float tanh_fast(float x) {
    float y;
    asm("tanh.approx.f32 %0, %1;" : "=f"(y) : "f"(x));
    return y;
}
__device__ __forceinline__ float sigmoidf(float x) {
    return 1.0f / (1.0f + expf(-x));
}
__device__ __forceinline__ uint32_t f2tf(float x) {
    uint32_t u;
    asm("cvt.rna.tf32.f32 %0, %1;" : "=r"(u) : "f"(x));
    return u;
}

// ---------------- prep ----------------
__global__ void conv_f2h(const float* __restrict__ src, __half* __restrict__ dst, int n8) {
    int i = blockIdx.x * blockDim.x + threadIdx.x;
    if (i >= n8) return;
    float4 a = reinterpret_cast<const float4*>(src)[2 * i];
    float4 b = reinterpret_cast<const float4*>(src)[2 * i + 1];
    __half2* d = reinterpret_cast<__half2*>(dst) + 4 * (size_t)i;
    d[0] = __floats2half2_rn(a.x, a.y);
    d[1] = __floats2half2_rn(a.z, a.w);
    d[2] = __floats2half2_rn(b.x, b.y);
    d[3] = __floats2half2_rn(b.z, b.w);
}
__global__ void build_wcat_kernel(const float* __restrict__ Wih,
                                  const float* __restrict__ Whh) {
    int idx = blockIdx.x * blockDim.x + threadIdx.x;
    if (idx >= 4 * Hn * XCn) return;
    int j = idx >> 10;            // interleaved row [0,2048)
    int k = idx & 1023;
    int gate = j & 3, n = j >> 2;
    int r = gate * Hn + n;
    float v = (k < Dn) ? Wih[(size_t)r * DCn + k] : Whh[(size_t)r * Hn + (k - Dn)];
    g_Wcat[idx] = v;
}
__global__ void build_ohb_kernel(const float* __restrict__ Wih,
                                 const float* __restrict__ bih,
                                 const float* __restrict__ bhh) {
    int idx = blockIdx.x * blockDim.x + threadIdx.x;
    if (idx >= Cn * 4 * Hn) return;
    int c = idx / (4 * Hn);
    int j = idx % (4 * Hn);
    int gate = j & 3, n = j >> 2;
    int r = gate * Hn + n;
    g_ohb[idx] = Wih[(size_t)r * DCn + Dn + c] + bih[r] + bhh[r];
}
__global__ void init_state_kernel() {
    int i = blockIdx.x * blockDim.x + threadIdx.x;
    if (i < Bn * Hn) {
        g_c[i] = 0.0f;
        g_xcat[(i / Hn) * XCn + Dn + (i % Hn)] = 0.0f;
    }
}

// ---------------- tf32 tensor-core GEMM (round-2 proven core) ----------------
// C[m,n] = sum_k A[m,k]*B[n,k]. Tile 128x64x32, 256 thr, warps 4m x 2n (32x32).
// MODE 1: fp32 C + bias, gridDim.z split-K (bias z==0 only).
// MODE 3: fused LSTM epilogue (no C write).
// MODE 4: fp16 C store (Hp).
template <int MODE>
__global__ __launch_bounds__(256)
void gemm_tf32(const float* __restrict__ A, int lda,
               const float* __restrict__ B, int ldb,
               const float* __restrict__ bias,
               void* __restrict__ Cv, int ldc,
               int M, int N, int K,
               const int* __restrict__ text, int s)
{
    // smem: As[128][36] + Bs[64][36] uint32 = 27648 B; MODE3 gbuf 128*72*4 = 36864 B
    __shared__ __align__(16) unsigned char smraw[36864];
    uint32_t (*As)[36] = reinterpret_cast<uint32_t(*)[36]>(smraw);
    uint32_t (*Bs)[36] = reinterpret_cast<uint32_t(*)[36]>(smraw + 128 * 36 * 4);

    const int tid = threadIdx.x;
    const int warp = tid >> 5, lane = tid & 31;
    const int g = lane >> 2, tig = lane & 3;
    const int wm = warp >> 1, wn = warp & 1;
    const int m0 = blockIdx.y * 128, n0 = blockIdx.x * 64;

    if (MODE == 1) {
        int z = blockIdx.z;
        A += (size_t)z * K;
        B += (size_t)z * K;
        Cv = (void*)((float*)Cv + (size_t)z * M * ldc);
        if (z != 0) bias = nullptr;
    }

    const float* Aptr = A + (size_t)m0 * lda;
    const float* Bptr = B + (size_t)n0 * ldb;

    float4 pa[4], pb[2];
    float acc[2][4][4];
#pragma unroll
    for (int i = 0; i < 2; i++)
#pragma unroll
        for (int j = 0; j < 4; j++)
#pragma unroll
            for (int l = 0; l < 4; l++) acc[i][j][l] = 0.0f;

    // prefetch tile 0
#pragma unroll
    for (int v = 0; v < 4; v++) {
        int f = tid + v * 256;
        pa[v] = *reinterpret_cast<const float4*>(Aptr + (size_t)(f >> 3) * lda + ((f & 7) << 2));
    }
#pragma unroll
    for (int v = 0; v < 2; v++) {
        int f = tid + v * 256;
        pb[v] = *reinterpret_cast<const float4*>(Bptr + (size_t)(f >> 3) * ldb + ((f & 7) << 2));
    }

    for (int k0 = 0; k0 < K; k0 += 32) {
#pragma unroll
        for (int v = 0; v < 4; v++) {
            int f = tid + v * 256; int r = f >> 3, c = (f & 7) << 2;
            uint4 q = make_uint4(f2tf(pa[v].x), f2tf(pa[v].y), f2tf(pa[v].z), f2tf(pa[v].w));
            *reinterpret_cast<uint4*>(&As[r][c]) = q;
        }
#pragma unroll
        for (int v = 0; v < 2; v++) {
            int f = tid + v * 256; int r = f >> 3, c = (f & 7) << 2;
            uint4 q = make_uint4(f2tf(pb[v].x), f2tf(pb[v].y), f2tf(pb[v].z), f2tf(pb[v].w));
            *reinterpret_cast<uint4*>(&Bs[r][c]) = q;
        }
        __syncthreads();

        if (k0 + 32 < K) {
            const float* An = Aptr + k0 + 32;
            const float* Bnp = Bptr + k0 + 32;
#pragma unroll
            for (int v = 0; v < 4; v++) {
                int f = tid + v * 256;
                pa[v] = *reinterpret_cast<const float4*>(An + (size_t)(f >> 3) * lda + ((f & 7) << 2));
            }
#pragma unroll
            for (int v = 0; v < 2; v++) {
                int f = tid + v * 256;
                pb[v] = *reinterpret_cast<const float4*>(Bnp + (size_t)(f >> 3) * ldb + ((f & 7) << 2));
            }
        }

#pragma unroll
        for (int ks = 0; ks < 4; ks++) {
            const int kk = ks * 8;
            uint32_t af[2][4], bf[4][2];
#pragma unroll
            for (int mt = 0; mt < 2; mt++) {
                int mb = wm * 32 + mt * 16;
                af[mt][0] = As[mb + g][kk + tig];
                af[mt][1] = As[mb + g + 8][kk + tig];
                af[mt][2] = As[mb + g][kk + tig + 4];
                af[mt][3] = As[mb + g + 8][kk + tig + 4];
            }
#pragma unroll
            for (int nt = 0; nt < 4; nt++) {
                int nb = wn * 32 + nt * 8 + g;
                bf[nt][0] = Bs[nb][kk + tig];
                bf[nt][1] = Bs[nb][kk + tig + 4];
            }
#pragma unroll
            for (int mt = 0; mt < 2; mt++)
#pragma unroll
                for (int nt = 0; nt < 4; nt++)
                    asm volatile(
                        "mma.sync.aligned.m16n8k8.row.col.f32.tf32.tf32.f32 "
                        "{%0,%1,%2,%3}, {%4,%5,%6,%7}, {%8,%9}, {%0,%1,%2,%3};"
                        : "+f"(acc[mt][nt][0]), "+f"(acc[mt][nt][1]),
                          "+f"(acc[mt][nt][2]), "+f"(acc[mt][nt][3])
                        : "r"(af[mt][0]), "r"(af[mt][1]), "r"(af[mt][2]), "r"(af[mt][3]),
                          "r"(bf[nt][0]), "r"(bf[nt][1]));
        }
        __syncthreads();
    }

    if (MODE == 3) {
        // fused LSTM epilogue: stage gates tile [128][64 interleaved] in smem
        float* gbuf = reinterpret_cast<float*>(smraw);   // [128][72]
#pragma unroll
        for (int mt = 0; mt < 2; mt++) {
            int row = wm * 32 + mt * 16 + g;
#pragma unroll
            for (int nt = 0; nt < 4; nt++) {
                int col = wn * 32 + nt * 8 + 2 * tig;
                gbuf[row * 72 + col]           = acc[mt][nt][0];
                gbuf[row * 72 + col + 1]       = acc[mt][nt][1];
                gbuf[(row + 8) * 72 + col]     = acc[mt][nt][2];
                gbuf[(row + 8) * 72 + col + 1] = acc[mt][nt][3];
            }
        }
        __syncthreads();
#pragma unroll
        for (int p = 0; p < 8; p++) {
            int idx = p * 256 + tid;
            int bl = idx >> 4, nl = idx & 15;
            int b = m0 + bl;
            int ng = (n0 >> 2) + nl;
            float4 gv = *reinterpret_cast<const float4*>(&gbuf[bl * 72 + 4 * nl]);
            int tok = text[b * Sn + s];
            float4 ov = *reinterpret_cast<const float4*>(&g_ohb[(size_t)tok * 4 * Hn + 4 * ng]);
            float ig = gv.x + ov.x;
            float fg = gv.y + ov.y;
            float gg = gv.z + ov.z;
            float og = gv.w + ov.w;
            float c_old = g_c[b * Hn + ng];
            float cn = sigmoidf(fg) * c_old + sigmoidf(ig) * tanhf(gg);
            float hn = sigmoidf(og) * tanhf(cn);
            g_c[b * Hn + ng] = cn;
            g_xcat[b * XCn + Dn + ng] = hn;
            g_hs[((size_t)b * Sn + s) * Hn + ng] = hn;
        }
        return;
    }

#pragma unroll
    for (int mt = 0; mt < 2; mt++) {
        int row = m0 + wm * 32 + mt * 16 + g;
#pragma unroll
        for (int nt = 0; nt < 4; nt++) {
            int col = n0 + wn * 32 + nt * 8 + 2 * tig;
            if (MODE == 4) {
                __half* C = (__half*)Cv;
                *reinterpret_cast<__half2*>(&C[(size_t)row * ldc + col]) =
                    __floats2half2_rn(acc[mt][nt][0], acc[mt][nt][1]);
                *reinterpret_cast<__half2*>(&C[(size_t)(row + 8) * ldc + col]) =
                    __floats2half2_rn(acc[mt][nt][2], acc[mt][nt][3]);
            } else {
                float* C = (float*)Cv;
                float b0 = 0.f, b1 = 0.f;
                if (bias) { b0 = bias[col]; b1 = bias[col + 1]; }
                *reinterpret_cast<float2*>(&C[(size_t)row * ldc + col]) =
                    make_float2(acc[mt][nt][0] + b0, acc[mt][nt][1] + b1);
                *reinterpret_cast<float2*>(&C[(size_t)(row + 8) * ldc + col]) =
                    make_float2(acc[mt][nt][2] + b0, acc[mt][nt][3] + b1);
            }
        }
    }
}

// ---------------- fp32 SGEMM (generator: protects output precision) ----------------
template <bool BIAS>
__global__ __launch_bounds__(256)
void sgemm_nt(const float* __restrict__ A, int lda,
              const float* __restrict__ Bm, int ldb,
              const float* __restrict__ bias,
              float* __restrict__ C, int ldc,
              int M, int N, int K)
{
    constexpr int BM = 128, BN = 64, BK = 16, TM = 8, TN = 4;
    __shared__ float As[BK][BM];
    __shared__ float Bs[BK][BN];

    const int tid = threadIdx.x;
    const int tx = tid % (BN / TN);
    const int ty = tid / (BN / TN);
    const int m0 = blockIdx.y * BM;
    const int n0 = blockIdx.x * BN;

    float acc[TM][TN];
#pragma unroll
    for (int i = 0; i < TM; i++)
#pragma unroll
        for (int j = 0; j < TN; j++) acc[i][j] = 0.0f;

    for (int k0 = 0; k0 < K; k0 += BK) {
#pragma unroll
        for (int v = 0; v < 2; v++) {
            int f = tid + v * 256;
            int r = f >> 2;
            int c4 = (f & 3) << 2;
            float4 val = make_float4(0.f, 0.f, 0.f, 0.f);
            int gr = m0 + r;
            if (gr < M)
                val = *reinterpret_cast<const float4*>(&A[(size_t)gr * lda + k0 + c4]);
            As[c4 + 0][r] = val.x; As[c4 + 1][r] = val.y;
            As[c4 + 2][r] = val.z; As[c4 + 3][r] = val.w;
        }
        {
            int f = tid;
            int r = f >> 2;
            int c4 = (f & 3) << 2;
            float4 val = make_float4(0.f, 0.f, 0.f, 0.f);
            int gr = n0 + r;
            if (gr < N)
                val = *reinterpret_cast<const float4*>(&Bm[(size_t)gr * ldb + k0 + c4]);
            Bs[c4 + 0][r] = val.x; Bs[c4 + 1][r] = val.y;
            Bs[c4 + 2][r] = val.z; Bs[c4 + 3][r] = val.w;
        }
        __syncthreads();
#pragma unroll
        for (int kk = 0; kk < BK; kk++) {
            float ra[TM], rb[TN];
#pragma unroll
            for (int i = 0; i < TM; i++) ra[i] = As[kk][ty * TM + i];
#pragma unroll
            for (int j = 0; j < TN; j++) rb[j] = Bs[kk][tx * TN + j];
#pragma unroll
            for (int i = 0; i < TM; i++)
#pragma unroll
                for (int j = 0; j < TN; j++)
                    acc[i][j] = fmaf(ra[i], rb[j], acc[i][j]);
        }
        __syncthreads();
    }
#pragma unroll
    for (int i = 0; i < TM; i++) {
        int m = m0 + ty * TM + i;
        if (m >= M) continue;
#pragma unroll
        for (int j = 0; j < TN; j++) {
            int n = n0 + tx * TN + j;
            if (n >= N) continue;
            float v = acc[i][j];
            if (BIAS) v += bias[n];
            C[(size_t)m * ldc + n] = v;
        }
    }
}

// ---------------- fused attention (fp16 Hp / fp16 batch_H, fp32 everything else) ----
__global__ __launch_bounds__(256)
void attn_kernel(const float* __restrict__ Ws)
{
    const int b = blockIdx.x;
    __shared__ float2 ph2_s[256];
    __shared__ float2 ws2_s[256];
    __shared__ float e_s[Tn];
    __shared__ float alpha_s[Tn];

    const int tid = threadIdx.x;
    {
        const float2* p0 = reinterpret_cast<const float2*>(g_ph + b * Hn);
        const float2* p1 = reinterpret_cast<const float2*>(g_ph + Bn * Hn + b * Hn);
        float2 a = p0[tid], c = p1[tid];
        ph2_s[tid] = make_float2(a.x + c.x, a.y + c.y);
        ws2_s[tid] = reinterpret_cast<const float2*>(Ws)[tid];
    }
    __syncthreads();

    const int warp = tid >> 5, lane = tid & 31;

    for (int t = warp; t < Tn; t += 8) {
        const __half2* hp2 = reinterpret_cast<const __half2*>(
            g_Hp16 + (size_t)b * Tn * Hn + (size_t)t * Hn);
        float a = 0.0f;
#pragma unroll 4
        for (int h2 = lane; h2 < 256; h2 += 32) {
            float2 v = __half22float2(hp2[h2]);
            float2 p = ph2_s[h2], w = ws2_s[h2];
            a = fmaf(tanh_fast(v.x + p.x), w.x, a);
            a = fmaf(tanh_fast(v.y + p.y), w.y, a);
        }
#pragma unroll
        for (int o = 16; o > 0; o >>= 1)
            a += __shfl_xor_sync(0xffffffffu, a, o);
        if (lane == 0) e_s[t] = a;
    }
    __syncthreads();

    if (warp == 0) {
        float e0 = e_s[lane], e1 = e_s[lane + 32];
        float m = fmaxf(e0, e1);
#pragma unroll
        for (int o = 16; o > 0; o >>= 1)
            m = fmaxf(m, __shfl_xor_sync(0xffffffffu, m, o));
        float x0 = expf(e0 - m), x1 = expf(e1 - m);
        float sum = x0 + x1;
#pragma unroll
        for (int o = 16; o > 0; o >>= 1)
            sum += __shfl_xor_sync(0xffffffffu, sum, o);
        float inv = 1.0f / sum;
        alpha_s[lane] = x0 * inv;
        alpha_s[lane + 32] = x1 * inv;
    }
    __syncthreads();

    const __half2* bh2 = reinterpret_cast<const __half2*>(g_bh16 + (size_t)b * Tn * Dn);
    float ax = 0.0f, ay = 0.0f;
#pragma unroll 8
    for (int t = 0; t < Tn; t++) {
        float al = alpha_s[t];
        float2 v = __half22float2(bh2[t * 256 + tid]);
        ax = fmaf(al, v.x, ax);
        ay = fmaf(al, v.y, ay);
    }
    reinterpret_cast<float2*>(g_xcat + (size_t)b * XCn)[tid] = make_float2(ax, ay);
}

// ---------------- launch ----------------
extern "C" void kernel_launch(void* const* d_in, const int* in_sizes, int n_in,
                              void* d_out, int out_size)
{
    const float* batch_H = (const float*)d_in[0];
    const int*   text    = (const int*)  d_in[1];
    const float* Wi      = (const float*)d_in[2];
    const float* Wh      = (const float*)d_in[3];
    const float* bh      = (const float*)d_in[4];
    const float* Ws      = (const float*)d_in[5];
    const float* Wih     = (const float*)d_in[6];
    const float* Whh     = (const float*)d_in[7];
    const float* bih     = (const float*)d_in[8];
    const float* bhh     = (const float*)d_in[9];
    const float* Wg      = (const float*)d_in[10];
    const float* bg      = (const float*)d_in[11];
    float* out = (float*)d_out;

    __half *Hp16, *bh16;
    float *ph, *xcat, *hs, *Wcat;
    cudaGetSymbolAddress((void**)&Hp16, g_Hp16);
    cudaGetSymbolAddress((void**)&bh16, g_bh16);
    cudaGetSymbolAddress((void**)&ph,   g_ph);
    cudaGetSymbolAddress((void**)&xcat, g_xcat);
    cudaGetSymbolAddress((void**)&hs,   g_hs);
    cudaGetSymbolAddress((void**)&Wcat, g_Wcat);

    // prep
    conv_f2h<<<(Bn * Tn * Dn / 8 + 255) / 256, 256>>>(batch_H, bh16, Bn * Tn * Dn / 8);
    build_wcat_kernel<<<(4 * Hn * XCn + 255) / 256, 256>>>(Wih, Whh);
    build_ohb_kernel<<<(Cn * 4 * Hn + 255) / 256, 256>>>(Wih, bih, bhh);
    init_state_kernel<<<(Bn * Hn + 255) / 256, 256>>>();

    // Hp16 = batch_H @ Wi^T (tf32 compute, fp16 store)
    gemm_tf32<4><<<dim3(Hn / 64, (Bn * Tn) / 128), 256>>>(
        batch_H, Dn, Wi, Dn, nullptr, Hp16, Hn, Bn * Tn, Hn, Dn, nullptr, 0);

    for (int s = 0; s < Sn; s++) {
        // ph halves: z in {0,1}, K=256 each (bias on z=0)
        gemm_tf32<1><<<dim3(Hn / 64, Bn / 128, 2), 256>>>(
            xcat + Dn, XCn, Wh, Hn, bh, ph, Hn, Bn, Hn, 256, nullptr, 0);

        attn_kernel<<<Bn, 256>>>(Ws);

        // gates (interleaved Wcat) + fused LSTM
        gemm_tf32<3><<<dim3(4 * Hn / 64, Bn / 128), 256>>>(
            xcat, XCn, Wcat, XCn, nullptr, nullptr, 0, Bn, 4 * Hn, XCn, text, s);
    }

    // probs = hs @ Wg^T + bg  (fp32 to protect output precision)
    sgemm_nt<true><<<dim3((Cn + 63) / 64, (Bn * Sn) / 128), 256>>>(
        hs, Hn, Wg, Hn, bg, out, Cn, Bn * Sn, Cn, Hn);
}

// round 6
// speedup vs baseline: 1.6208x; 1.2485x over previous
#include <cuda_runtime.h>
#include <cuda_fp16.h>
#include <math.h>
#include <stdint.h>

#define Bn 1024
#define Tn 64
#define Dn 512
#define Hn 512
#define Cn 96
#define Sn 21
#define DCn (Dn + Cn)   // 608
#define XCn (Dn + Hn)   // 1024

// ---------------- scratch (device globals) ----------------
__device__ __half g_Hp16[(size_t)Bn * Tn * Hn];     // attention score input (fp16 ok)
__device__ __half g_bh16[(size_t)Bn * Tn * Dn];     // ctx accumulation input (fp16 ok)
__device__ float  g_c[Bn * Hn];
__device__ float  g_ph[2 * Bn * Hn];                // split-K halves
__device__ float  g_xcat[Bn * XCn];                 // [ctx | h] fp32
__device__ float  g_hs[(size_t)Bn * Sn * Hn];       // fp32 (output path)
__device__ float  g_Wcat[(size_t)4 * Hn * XCn];     // interleaved rows j=4n+gate
__device__ float  g_ohb[Cn * 4 * Hn];               // Wih one-hot col + biases, interleaved

// ---------------- helpers ----------------
__device__ __forceinline__ float tanh_fast(float x) {
    float y;
    asm("tanh.approx.f32 %0, %1;" : "=f"(y) : "f"(x));
    return y;
}
__device__ __forceinline__ float sigmoidf(float x) {
    return 1.0f / (1.0f + expf(-x));
}

// ---------------- prep ----------------
__global__ void conv_f2h(const float* __restrict__ src, __half* __restrict__ dst, int n8) {
    int i = blockIdx.x * blockDim.x + threadIdx.x;
    if (i >= n8) return;
    float4 a = reinterpret_cast<const float4*>(src)[2 * i];
    float4 b = reinterpret_cast<const float4*>(src)[2 * i + 1];
    __half2* d = reinterpret_cast<__half2*>(dst) + 4 * (size_t)i;
    d[0] = __floats2half2_rn(a.x, a.y);
    d[1] = __floats2half2_rn(a.z, a.w);
    d[2] = __floats2half2_rn(b.x, b.y);
    d[3] = __floats2half2_rn(b.z, b.w);
}
__global__ void build_wcat_kernel(const float* __restrict__ Wih,
                                  const float* __restrict__ Whh) {
    int idx = blockIdx.x * blockDim.x + threadIdx.x;
    if (idx >= 4 * Hn * XCn) return;
    int j = idx >> 10;            // interleaved row [0,2048)
    int k = idx & 1023;
    int gate = j & 3, n = j >> 2;
    int r = gate * Hn + n;
    float v = (k < Dn) ? Wih[(size_t)r * DCn + k] : Whh[(size_t)r * Hn + (k - Dn)];
    g_Wcat[idx] = v;
}
__global__ void build_ohb_kernel(const float* __restrict__ Wih,
                                 const float* __restrict__ bih,
                                 const float* __restrict__ bhh) {
    int idx = blockIdx.x * blockDim.x + threadIdx.x;
    if (idx >= Cn * 4 * Hn) return;
    int c = idx / (4 * Hn);
    int j = idx % (4 * Hn);
    int gate = j & 3, n = j >> 2;
    int r = gate * Hn + n;
    g_ohb[idx] = Wih[(size_t)r * DCn + Dn + c] + bih[r] + bhh[r];
}
__global__ void init_state_kernel() {
    int i = blockIdx.x * blockDim.x + threadIdx.x;
    if (i < Bn * Hn) {
        g_c[i] = 0.0f;
        g_xcat[(i / Hn) * XCn + Dn + (i % Hn)] = 0.0f;
    }
}

// ---------------- fp16-operand tensor-core GEMM (fp32 in/out, fp32 accum) --------
// C[m,n] = sum_k A[m,k]*B[n,k]. A,B fp32 in gmem; converted to fp16 on smem store.
// Tile 128x64x32, 256 thr, warps 4m x 2n (32x32 per warp), mma m16n8k16.
// MODE 1: fp32 C + bias, gridDim.z split-K (bias z==0 only).
// MODE 2: fp32 C + bias, ragged-N guard (Np).
// MODE 3: fused LSTM epilogue (no C write).
// MODE 4: fp16 C store (Hp).
template <int MODE>
__global__ __launch_bounds__(256)
void hgemm(const float* __restrict__ A, int lda,
           const float* __restrict__ B, int ldb,
           const float* __restrict__ bias,
           void* __restrict__ Cv, int ldc,
           int M, int Np, int K,
           const int* __restrict__ text, int s)
{
    // As[128][40] half (10240 B) + Bs[64][40] half (5120 B) = 15360 B
    // MODE 3 epilogue reuses as float gbuf[128][72] = 36864 B
    __shared__ __align__(16) unsigned char smraw[36864];
    __half* As = reinterpret_cast<__half*>(smraw);                  // stride 40
    __half* Bs = reinterpret_cast<__half*>(smraw + 128 * 40 * 2);   // stride 40

    const int tid = threadIdx.x;
    const int warp = tid >> 5, lane = tid & 31;
    const int g = lane >> 2, tig = lane & 3;
    const int wm = warp >> 1, wn = warp & 1;
    const int m0 = blockIdx.y * 128, n0 = blockIdx.x * 64;

    if (MODE == 1) {
        int z = blockIdx.z;
        A += (size_t)z * K;
        B += (size_t)z * K;
        Cv = (void*)((float*)Cv + (size_t)z * M * ldc);
        if (z != 0) bias = nullptr;
    }

    const float* Aptr = A + (size_t)m0 * lda;
    const float* Bptr = B + (size_t)n0 * ldb;

    float4 pa[4], pb[2];
    float acc[2][4][4];
#pragma unroll
    for (int i = 0; i < 2; i++)
#pragma unroll
        for (int j = 0; j < 4; j++)
#pragma unroll
            for (int l = 0; l < 4; l++) acc[i][j][l] = 0.0f;

    // prefetch tile 0
#pragma unroll
    for (int v = 0; v < 4; v++) {
        int f = tid + v * 256;
        pa[v] = *reinterpret_cast<const float4*>(Aptr + (size_t)(f >> 3) * lda + ((f & 7) << 2));
    }
#pragma unroll
    for (int v = 0; v < 2; v++) {
        int f = tid + v * 256;
        if (MODE == 2 && n0 + (f >> 3) >= Np) pb[v] = make_float4(0.f, 0.f, 0.f, 0.f);
        else pb[v] = *reinterpret_cast<const float4*>(Bptr + (size_t)(f >> 3) * ldb + ((f & 7) << 2));
    }

    for (int k0 = 0; k0 < K; k0 += 32) {
        // convert fp32 -> fp16 and store to smem
#pragma unroll
        for (int v = 0; v < 4; v++) {
            int f = tid + v * 256; int r = f >> 3, c = (f & 7) << 2;
            __half2 h0 = __floats2half2_rn(pa[v].x, pa[v].y);
            __half2 h1 = __floats2half2_rn(pa[v].z, pa[v].w);
            *reinterpret_cast<__half2*>(&As[r * 40 + c])     = h0;
            *reinterpret_cast<__half2*>(&As[r * 40 + c + 2]) = h1;
        }
#pragma unroll
        for (int v = 0; v < 2; v++) {
            int f = tid + v * 256; int r = f >> 3, c = (f & 7) << 2;
            __half2 h0 = __floats2half2_rn(pb[v].x, pb[v].y);
            __half2 h1 = __floats2half2_rn(pb[v].z, pb[v].w);
            *reinterpret_cast<__half2*>(&Bs[r * 40 + c])     = h0;
            *reinterpret_cast<__half2*>(&Bs[r * 40 + c + 2]) = h1;
        }
        __syncthreads();

        // prefetch next
        if (k0 + 32 < K) {
            const float* An = Aptr + k0 + 32;
            const float* Bnp = Bptr + k0 + 32;
#pragma unroll
            for (int v = 0; v < 4; v++) {
                int f = tid + v * 256;
                pa[v] = *reinterpret_cast<const float4*>(An + (size_t)(f >> 3) * lda + ((f & 7) << 2));
            }
#pragma unroll
            for (int v = 0; v < 2; v++) {
                int f = tid + v * 256;
                if (MODE == 2 && n0 + (f >> 3) >= Np) pb[v] = make_float4(0.f, 0.f, 0.f, 0.f);
                else pb[v] = *reinterpret_cast<const float4*>(Bnp + (size_t)(f >> 3) * ldb + ((f & 7) << 2));
            }
        }

        // compute: 2 k-steps of 16
#pragma unroll
        for (int ks = 0; ks < 2; ks++) {
            const int kk = ks * 16;
            uint32_t af[2][4], bf[4][2];
#pragma unroll
            for (int mt = 0; mt < 2; mt++) {
                int mb = wm * 32 + mt * 16;
                af[mt][0] = *reinterpret_cast<const uint32_t*>(&As[(mb + g) * 40 + kk + 2 * tig]);
                af[mt][1] = *reinterpret_cast<const uint32_t*>(&As[(mb + g + 8) * 40 + kk + 2 * tig]);
                af[mt][2] = *reinterpret_cast<const uint32_t*>(&As[(mb + g) * 40 + kk + 2 * tig + 8]);
                af[mt][3] = *reinterpret_cast<const uint32_t*>(&As[(mb + g + 8) * 40 + kk + 2 * tig + 8]);
            }
#pragma unroll
            for (int nt = 0; nt < 4; nt++) {
                int nb = wn * 32 + nt * 8 + g;
                bf[nt][0] = *reinterpret_cast<const uint32_t*>(&Bs[nb * 40 + kk + 2 * tig]);
                bf[nt][1] = *reinterpret_cast<const uint32_t*>(&Bs[nb * 40 + kk + 2 * tig + 8]);
            }
#pragma unroll
            for (int mt = 0; mt < 2; mt++)
#pragma unroll
                for (int nt = 0; nt < 4; nt++)
                    asm volatile(
                        "mma.sync.aligned.m16n8k16.row.col.f32.f16.f16.f32 "
                        "{%0,%1,%2,%3}, {%4,%5,%6,%7}, {%8,%9}, {%0,%1,%2,%3};"
                        : "+f"(acc[mt][nt][0]), "+f"(acc[mt][nt][1]),
                          "+f"(acc[mt][nt][2]), "+f"(acc[mt][nt][3])
                        : "r"(af[mt][0]), "r"(af[mt][1]), "r"(af[mt][2]), "r"(af[mt][3]),
                          "r"(bf[nt][0]), "r"(bf[nt][1]));
        }
        __syncthreads();
    }

    if (MODE == 3) {
        // fused LSTM epilogue: stage gates tile [128][64 interleaved] in smem
        float* gbuf = reinterpret_cast<float*>(smraw);   // [128][72]
#pragma unroll
        for (int mt = 0; mt < 2; mt++) {
            int row = wm * 32 + mt * 16 + g;
#pragma unroll
            for (int nt = 0; nt < 4; nt++) {
                int col = wn * 32 + nt * 8 + 2 * tig;
                gbuf[row * 72 + col]           = acc[mt][nt][0];
                gbuf[row * 72 + col + 1]       = acc[mt][nt][1];
                gbuf[(row + 8) * 72 + col]     = acc[mt][nt][2];
                gbuf[(row + 8) * 72 + col + 1] = acc[mt][nt][3];
            }
        }
        __syncthreads();
#pragma unroll
        for (int p = 0; p < 8; p++) {
            int idx = p * 256 + tid;
            int bl = idx >> 4, nl = idx & 15;
            int b = m0 + bl;
            int ng = (n0 >> 2) + nl;
            float4 gv = *reinterpret_cast<const float4*>(&gbuf[bl * 72 + 4 * nl]);
            int tok = text[b * Sn + s];
            float4 ov = *reinterpret_cast<const float4*>(&g_ohb[(size_t)tok * 4 * Hn + 4 * ng]);
            float ig = gv.x + ov.x;
            float fg = gv.y + ov.y;
            float gg = gv.z + ov.z;
            float og = gv.w + ov.w;
            float c_old = g_c[b * Hn + ng];
            float cn = sigmoidf(fg) * c_old + sigmoidf(ig) * tanhf(gg);
            float hn = sigmoidf(og) * tanhf(cn);
            g_c[b * Hn + ng] = cn;
            g_xcat[b * XCn + Dn + ng] = hn;
            g_hs[((size_t)b * Sn + s) * Hn + ng] = hn;
        }
        return;
    }

#pragma unroll
    for (int mt = 0; mt < 2; mt++) {
        int row = m0 + wm * 32 + mt * 16 + g;
#pragma unroll
        for (int nt = 0; nt < 4; nt++) {
            int col = n0 + wn * 32 + nt * 8 + 2 * tig;
            if (MODE == 2 && col >= Np) continue;
            if (MODE == 4) {
                __half* C = (__half*)Cv;
                *reinterpret_cast<__half2*>(&C[(size_t)row * ldc + col]) =
                    __floats2half2_rn(acc[mt][nt][0], acc[mt][nt][1]);
                *reinterpret_cast<__half2*>(&C[(size_t)(row + 8) * ldc + col]) =
                    __floats2half2_rn(acc[mt][nt][2], acc[mt][nt][3]);
            } else {
                float* C = (float*)Cv;
                float b0 = 0.f, b1 = 0.f;
                if (bias) { b0 = bias[col]; b1 = bias[col + 1]; }
                *reinterpret_cast<float2*>(&C[(size_t)row * ldc + col]) =
                    make_float2(acc[mt][nt][0] + b0, acc[mt][nt][1] + b1);
                *reinterpret_cast<float2*>(&C[(size_t)(row + 8) * ldc + col]) =
                    make_float2(acc[mt][nt][2] + b0, acc[mt][nt][3] + b1);
            }
        }
    }
}

// ---------------- fused attention (fp16 Hp / fp16 batch_H, fp32 everything else) ----
__global__ __launch_bounds__(256)
void attn_kernel(const float* __restrict__ Ws)
{
    const int b = blockIdx.x;
    __shared__ float2 ph2_s[256];
    __shared__ float2 ws2_s[256];
    __shared__ float e_s[Tn];
    __shared__ float alpha_s[Tn];

    const int tid = threadIdx.x;
    {
        const float2* p0 = reinterpret_cast<const float2*>(g_ph + b * Hn);
        const float2* p1 = reinterpret_cast<const float2*>(g_ph + Bn * Hn + b * Hn);
        float2 a = p0[tid], c = p1[tid];
        ph2_s[tid] = make_float2(a.x + c.x, a.y + c.y);
        ws2_s[tid] = reinterpret_cast<const float2*>(Ws)[tid];
    }
    __syncthreads();

    const int warp = tid >> 5, lane = tid & 31;

    for (int t = warp; t < Tn; t += 8) {
        const __half2* hp2 = reinterpret_cast<const __half2*>(
            g_Hp16 + (size_t)b * Tn * Hn + (size_t)t * Hn);
        float a = 0.0f;
#pragma unroll 4
        for (int h2 = lane; h2 < 256; h2 += 32) {
            float2 v = __half22float2(hp2[h2]);
            float2 p = ph2_s[h2], w = ws2_s[h2];
            a = fmaf(tanh_fast(v.x + p.x), w.x, a);
            a = fmaf(tanh_fast(v.y + p.y), w.y, a);
        }
#pragma unroll
        for (int o = 16; o > 0; o >>= 1)
            a += __shfl_xor_sync(0xffffffffu, a, o);
        if (lane == 0) e_s[t] = a;
    }
    __syncthreads();

    if (warp == 0) {
        float e0 = e_s[lane], e1 = e_s[lane + 32];
        float m = fmaxf(e0, e1);
#pragma unroll
        for (int o = 16; o > 0; o >>= 1)
            m = fmaxf(m, __shfl_xor_sync(0xffffffffu, m, o));
        float x0 = expf(e0 - m), x1 = expf(e1 - m);
        float sum = x0 + x1;
#pragma unroll
        for (int o = 16; o > 0; o >>= 1)
            sum += __shfl_xor_sync(0xffffffffu, sum, o);
        float inv = 1.0f / sum;
        alpha_s[lane] = x0 * inv;
        alpha_s[lane + 32] = x1 * inv;
    }
    __syncthreads();

    const __half2* bh2 = reinterpret_cast<const __half2*>(g_bh16 + (size_t)b * Tn * Dn);
    float ax = 0.0f, ay = 0.0f;
#pragma unroll 8
    for (int t = 0; t < Tn; t++) {
        float al = alpha_s[t];
        float2 v = __half22float2(bh2[t * 256 + tid]);
        ax = fmaf(al, v.x, ax);
        ay = fmaf(al, v.y, ay);
    }
    reinterpret_cast<float2*>(g_xcat + (size_t)b * XCn)[tid] = make_float2(ax, ay);
}

// ---------------- launch ----------------
extern "C" void kernel_launch(void* const* d_in, const int* in_sizes, int n_in,
                              void* d_out, int out_size)
{
    const float* batch_H = (const float*)d_in[0];
    const int*   text    = (const int*)  d_in[1];
    const float* Wi      = (const float*)d_in[2];
    const float* Wh      = (const float*)d_in[3];
    const float* bh      = (const float*)d_in[4];
    const float* Ws      = (const float*)d_in[5];
    const float* Wih     = (const float*)d_in[6];
    const float* Whh     = (const float*)d_in[7];
    const float* bih     = (const float*)d_in[8];
    const float* bhh     = (const float*)d_in[9];
    const float* Wg      = (const float*)d_in[10];
    const float* bg      = (const float*)d_in[11];
    float* out = (float*)d_out;

    __half *Hp16, *bh16;
    float *ph, *xcat, *hs, *Wcat;
    cudaGetSymbolAddress((void**)&Hp16, g_Hp16);
    cudaGetSymbolAddress((void**)&bh16, g_bh16);
    cudaGetSymbolAddress((void**)&ph,   g_ph);
    cudaGetSymbolAddress((void**)&xcat, g_xcat);
    cudaGetSymbolAddress((void**)&hs,   g_hs);
    cudaGetSymbolAddress((void**)&Wcat, g_Wcat);

    // prep
    conv_f2h<<<(Bn * Tn * Dn / 8 + 255) / 256, 256>>>(batch_H, bh16, Bn * Tn * Dn / 8);
    build_wcat_kernel<<<(4 * Hn * XCn + 255) / 256, 256>>>(Wih, Whh);
    build_ohb_kernel<<<(Cn * 4 * Hn + 255) / 256, 256>>>(Wih, bih, bhh);
    init_state_kernel<<<(Bn * Hn + 255) / 256, 256>>>();

    // Hp16 = batch_H @ Wi^T (fp16 mma, fp16 store)
    hgemm<4><<<dim3(Hn / 64, (Bn * Tn) / 128), 256>>>(
        batch_H, Dn, Wi, Dn, nullptr, Hp16, Hn, Bn * Tn, Hn, Dn, nullptr, 0);

    for (int s = 0; s < Sn; s++) {
        // ph halves: z in {0,1}, K=256 each (bias on z=0)
        hgemm<1><<<dim3(Hn / 64, Bn / 128, 2), 256>>>(
            xcat + Dn, XCn, Wh, Hn, bh, ph, Hn, Bn, Hn, 256, nullptr, 0);

        attn_kernel<<<Bn, 256>>>(Ws);

        // gates (interleaved Wcat) + fused LSTM
        hgemm<3><<<dim3(4 * Hn / 64, Bn / 128), 256>>>(
            xcat, XCn, Wcat, XCn, nullptr, nullptr, 0, Bn, 4 * Hn, XCn, text, s);
    }

    // probs = hs @ Wg^T + bg  (fp16 mma, fp32 out, ragged N=96)
    hgemm<2><<<dim3(2, (Bn * Sn) / 128), 256>>>(
        hs, Hn, Wg, Hn, bg, out, Cn, Bn * Sn, Cn, Hn, nullptr, 0);
}